// round 1
// baseline (speedup 1.0000x reference)
#include <cuda_runtime.h>
#include <math.h>

#define MAX_NODES 50000
#define MAX_RELS  16
#define D 32

// Scratch (device globals; no allocation allowed)
__device__ float g_P[MAX_NODES * D * 4];   // [n][o][b] -> float4 per (n,o)
__device__ float g_u[MAX_NODES * D];       // init_fea @ A_w[0:32]
__device__ float g_v[MAX_NODES * D];       // init_fea @ A_w[32:64]
__device__ float g_agg[MAX_NODES * D];     // curr (self-loop) + scatter of a*msg
__device__ float g_t[MAX_RELS * D];        // attn_emb @ A_w[64:96] + A_b

// ---------------------------------------------------------------------------
// K0: per-relation attention bias table t[r][o]
// ---------------------------------------------------------------------------
__global__ void k_rel_t(const float* __restrict__ attn_emb,
                        const float* __restrict__ A_w,
                        const float* __restrict__ A_b) {
    int r = threadIdx.x >> 5;
    int o = threadIdx.x & 31;
    float acc = A_b[o];
#pragma unroll
    for (int k = 0; k < 32; k++)
        acc += attn_emb[r * 32 + k] * A_w[(64 + k) * 32 + o];
    g_t[r * 32 + o] = acc;
}

// ---------------------------------------------------------------------------
// K1: node stage. 4 nodes per warp. Computes:
//   init_fea = concat(feat, embed[idx]) @ transform        -> out[:,0,:]
//   P[b]     = init_fea @ weight[b]        (b = 0..3)
//   u        = init_fea @ A_w[0:32]
//   v        = init_fea @ A_w[32:64]
//   curr     = init_fea @ self_loop_weight -> g_agg init
// ---------------------------------------------------------------------------
__global__ void __launch_bounds__(256) k_node(
    const float* __restrict__ feat, const float* __restrict__ embed,
    const int* __restrict__ idx, const float* __restrict__ transform,
    const float* __restrict__ weight, const float* __restrict__ A_w,
    const float* __restrict__ selfw, float* __restrict__ out, int n_nodes) {
    __shared__ float sT[64 * 32];      // transform
    __shared__ float sW[4 * 32 * 32];  // basis weights
    __shared__ float sA[64 * 32];      // A_w rows 0..63
    __shared__ float sS[32 * 32];      // self loop

    int tid = threadIdx.x;
    for (int i = tid; i < 64 * 32; i += blockDim.x) sT[i] = transform[i];
    for (int i = tid; i < 4 * 32 * 32; i += blockDim.x) sW[i] = weight[i];
    for (int i = tid; i < 64 * 32; i += blockDim.x) sA[i] = A_w[i];
    for (int i = tid; i < 32 * 32; i += blockDim.x) sS[i] = selfw[i];
    __syncthreads();

    int warp = (blockIdx.x * blockDim.x + tid) >> 5;
    int lane = tid & 31;
    int n0 = warp * 4;
    if (n0 >= n_nodes) return;

    float f[4], g[4];
    bool val[4];
#pragma unroll
    for (int j = 0; j < 4; j++) {
        int n = n0 + j;
        val[j] = (n < n_nodes);
        if (val[j]) {
            f[j] = feat[n * 32 + lane];
            g[j] = embed[(long)idx[n] * 32 + lane];
        } else {
            f[j] = 0.f; g[j] = 0.f;
        }
    }

    // Phase A: init_fea (lane = output column)
    float fea[4] = {0.f, 0.f, 0.f, 0.f};
#pragma unroll
    for (int k = 0; k < 32; k++) {
        float t1 = sT[k * 32 + lane];
        float t2 = sT[(32 + k) * 32 + lane];
#pragma unroll
        for (int j = 0; j < 4; j++) {
            float fs = __shfl_sync(0xffffffffu, f[j], k);
            float gs = __shfl_sync(0xffffffffu, g[j], k);
            fea[j] += fs * t1 + gs * t2;
        }
    }

    // Phase B: 7 downstream projections of init_fea
    float P0[4] = {0,0,0,0}, P1[4] = {0,0,0,0}, P2[4] = {0,0,0,0}, P3[4] = {0,0,0,0};
    float u[4] = {0,0,0,0}, v[4] = {0,0,0,0}, c[4] = {0,0,0,0};
#pragma unroll
    for (int k = 0; k < 32; k++) {
        float w0 = sW[0 * 1024 + k * 32 + lane];
        float w1 = sW[1 * 1024 + k * 32 + lane];
        float w2 = sW[2 * 1024 + k * 32 + lane];
        float w3 = sW[3 * 1024 + k * 32 + lane];
        float wu = sA[k * 32 + lane];
        float wv = sA[(32 + k) * 32 + lane];
        float wc = sS[k * 32 + lane];
#pragma unroll
        for (int j = 0; j < 4; j++) {
            float s = __shfl_sync(0xffffffffu, fea[j], k);
            P0[j] += s * w0;
            P1[j] += s * w1;
            P2[j] += s * w2;
            P3[j] += s * w3;
            u[j] += s * wu;
            v[j] += s * wv;
            c[j] += s * wc;
        }
    }

#pragma unroll
    for (int j = 0; j < 4; j++) {
        if (!val[j]) continue;
        int n = n0 + j;
        out[(long)n * 64 + lane] = fea[j];                 // out[:,0,:]
        float4 p4 = make_float4(P0[j], P1[j], P2[j], P3[j]);
        reinterpret_cast<float4*>(g_P)[n * 32 + lane] = p4;
        g_u[n * 32 + lane] = u[j];
        g_v[n * 32 + lane] = v[j];
        g_agg[n * 32 + lane] = c[j];
    }
}

// ---------------------------------------------------------------------------
// K2: edge stage. One warp per edge (lane = output column).
//   msg = sum_b w_comp[type][b] * P[src][:,b]
//   z   = relu(u[src] + v[dst] + t[type])
//   a   = sigmoid(dot(z, B_w) + B_b)
//   atomicAdd(agg[dst], a * msg)
// ---------------------------------------------------------------------------
__global__ void __launch_bounds__(256) k_edge(
    const int* __restrict__ esrc, const int* __restrict__ edst,
    const int* __restrict__ etype, const float* __restrict__ w_comp,
    const float* __restrict__ B_w, const float* __restrict__ B_b, int n_edges) {
    __shared__ __align__(16) float s_wc[MAX_RELS * 4];
    __shared__ float s_t[MAX_RELS * 32];
    __shared__ float s_bw[32];
    __shared__ float s_bb;

    int tid = threadIdx.x;
    if (tid < MAX_RELS * 4) s_wc[tid] = w_comp[tid];
    for (int i = tid; i < MAX_RELS * 32; i += blockDim.x) s_t[i] = g_t[i];
    if (tid < 32) s_bw[tid] = B_w[tid];
    if (tid == 0) s_bb = B_b[0];
    __syncthreads();

    int e = (blockIdx.x * blockDim.x + tid) >> 5;
    int lane = tid & 31;
    if (e >= n_edges) return;

    int src = esrc[e];
    int dst = edst[e];
    int ty = etype[e];

    float4 p = reinterpret_cast<const float4*>(g_P)[src * 32 + lane];
    float4 cc = reinterpret_cast<const float4*>(s_wc)[ty];
    float msg = p.x * cc.x + p.y * cc.y + p.z * cc.z + p.w * cc.w;

    float z = g_u[src * 32 + lane] + g_v[dst * 32 + lane] + s_t[ty * 32 + lane];
    z = fmaxf(z, 0.f);

    float s = z * s_bw[lane];
#pragma unroll
    for (int off = 16; off; off >>= 1)
        s += __shfl_xor_sync(0xffffffffu, s, off);
    float a = 1.f / (1.f + expf(-(s + s_bb)));

    atomicAdd(&g_agg[dst * 32 + lane], a * msg);
}

// ---------------------------------------------------------------------------
// K3: h = relu(agg) -> out[:,1,:]
// ---------------------------------------------------------------------------
__global__ void k_final(float* __restrict__ out, int n_nodes) {
    int i = blockIdx.x * blockDim.x + threadIdx.x;
    if (i >= n_nodes * 32) return;
    int n = i >> 5;
    int o = i & 31;
    out[(long)n * 64 + 32 + o] = fmaxf(g_agg[i], 0.f);
}

extern "C" void kernel_launch(void* const* d_in, const int* in_sizes, int n_in,
                              void* d_out, int out_size) {
    const float* feat      = (const float*)d_in[0];
    const float* embed     = (const float*)d_in[1];
    const float* transform = (const float*)d_in[2];
    const float* weight    = (const float*)d_in[3];
    const float* w_comp    = (const float*)d_in[4];
    const float* selfw     = (const float*)d_in[5];
    const float* A_w       = (const float*)d_in[6];
    const float* A_b       = (const float*)d_in[7];
    const float* B_w       = (const float*)d_in[8];
    const float* B_b       = (const float*)d_in[9];
    const float* attn_emb  = (const float*)d_in[10];
    const int*   idx       = (const int*)d_in[11];
    const int*   esrc      = (const int*)d_in[12];
    const int*   edst      = (const int*)d_in[13];
    const int*   ety       = (const int*)d_in[14];
    float* out = (float*)d_out;

    int n_nodes = in_sizes[0] / 32;
    int n_edges = in_sizes[12];

    k_rel_t<<<1, MAX_RELS * 32>>>(attn_emb, A_w, A_b);

    int warps1 = (n_nodes + 3) / 4;
    int blocks1 = (warps1 * 32 + 255) / 256;
    k_node<<<blocks1, 256>>>(feat, embed, idx, transform, weight, A_w, selfw,
                             out, n_nodes);

    int blocks2 = (n_edges + 7) / 8;  // 8 warps/block, 1 edge/warp
    k_edge<<<blocks2, 256>>>(esrc, edst, ety, w_comp, B_w, B_b, n_edges);

    int blocks3 = (n_nodes * 32 + 255) / 256;
    k_final<<<blocks3, 256>>>(out, n_nodes);
}

// round 2
// speedup vs baseline: 1.4581x; 1.4581x over previous
#include <cuda_runtime.h>
#include <math.h>

#define MAX_NODES 50000
#define MAX_RELS  16
#define D 32

// Scratch (device globals; no allocation allowed)
__device__ __align__(16) float g_P[MAX_NODES * D * 4];   // [n][o][b] -> float4 per (n,o)
__device__ __align__(16) float g_u[MAX_NODES * D];       // init_fea @ A_w[0:32]
__device__ __align__(16) float g_v[MAX_NODES * D];       // init_fea @ A_w[32:64]
__device__ __align__(16) float g_agg[MAX_NODES * D];     // curr + scatter of a*msg
__device__ __align__(16) float g_t[MAX_RELS * D];        // attn_emb @ A_w[64:96] + A_b

// ---------------------------------------------------------------------------
// K0: per-relation attention bias table t[r][o]
// ---------------------------------------------------------------------------
__global__ void k_rel_t(const float* __restrict__ attn_emb,
                        const float* __restrict__ A_w,
                        const float* __restrict__ A_b) {
    int r = threadIdx.x >> 5;
    int o = threadIdx.x & 31;
    float acc = A_b[o];
#pragma unroll
    for (int k = 0; k < 32; k++)
        acc += attn_emb[r * 32 + k] * A_w[(64 + k) * 32 + o];
    g_t[r * 32 + o] = acc;
}

// ---------------------------------------------------------------------------
// K1: node stage. 4 nodes per warp.
// ---------------------------------------------------------------------------
__global__ void __launch_bounds__(256) k_node(
    const float* __restrict__ feat, const float* __restrict__ embed,
    const int* __restrict__ idx, const float* __restrict__ transform,
    const float* __restrict__ weight, const float* __restrict__ A_w,
    const float* __restrict__ selfw, float* __restrict__ out, int n_nodes) {
    __shared__ float sT[64 * 32];      // transform
    __shared__ float sW[4 * 32 * 32];  // basis weights
    __shared__ float sA[64 * 32];      // A_w rows 0..63
    __shared__ float sS[32 * 32];      // self loop

    int tid = threadIdx.x;
    for (int i = tid; i < 64 * 32; i += blockDim.x) sT[i] = transform[i];
    for (int i = tid; i < 4 * 32 * 32; i += blockDim.x) sW[i] = weight[i];
    for (int i = tid; i < 64 * 32; i += blockDim.x) sA[i] = A_w[i];
    for (int i = tid; i < 32 * 32; i += blockDim.x) sS[i] = selfw[i];
    __syncthreads();

    int warp = (blockIdx.x * blockDim.x + tid) >> 5;
    int lane = tid & 31;
    int n0 = warp * 4;
    if (n0 >= n_nodes) return;

    float f[4], g[4];
    bool val[4];
#pragma unroll
    for (int j = 0; j < 4; j++) {
        int n = n0 + j;
        val[j] = (n < n_nodes);
        if (val[j]) {
            f[j] = feat[n * 32 + lane];
            g[j] = embed[(long)idx[n] * 32 + lane];
        } else {
            f[j] = 0.f; g[j] = 0.f;
        }
    }

    // Phase A: init_fea (lane = output column)
    float fea[4] = {0.f, 0.f, 0.f, 0.f};
#pragma unroll
    for (int k = 0; k < 32; k++) {
        float t1 = sT[k * 32 + lane];
        float t2 = sT[(32 + k) * 32 + lane];
#pragma unroll
        for (int j = 0; j < 4; j++) {
            float fs = __shfl_sync(0xffffffffu, f[j], k);
            float gs = __shfl_sync(0xffffffffu, g[j], k);
            fea[j] += fs * t1 + gs * t2;
        }
    }

    // Phase B: 7 downstream projections of init_fea
    float P0[4] = {0,0,0,0}, P1[4] = {0,0,0,0}, P2[4] = {0,0,0,0}, P3[4] = {0,0,0,0};
    float u[4] = {0,0,0,0}, v[4] = {0,0,0,0}, c[4] = {0,0,0,0};
#pragma unroll
    for (int k = 0; k < 32; k++) {
        float w0 = sW[0 * 1024 + k * 32 + lane];
        float w1 = sW[1 * 1024 + k * 32 + lane];
        float w2 = sW[2 * 1024 + k * 32 + lane];
        float w3 = sW[3 * 1024 + k * 32 + lane];
        float wu = sA[k * 32 + lane];
        float wv = sA[(32 + k) * 32 + lane];
        float wc = sS[k * 32 + lane];
#pragma unroll
        for (int j = 0; j < 4; j++) {
            float s = __shfl_sync(0xffffffffu, fea[j], k);
            P0[j] += s * w0;
            P1[j] += s * w1;
            P2[j] += s * w2;
            P3[j] += s * w3;
            u[j] += s * wu;
            v[j] += s * wv;
            c[j] += s * wc;
        }
    }

#pragma unroll
    for (int j = 0; j < 4; j++) {
        if (!val[j]) continue;
        int n = n0 + j;
        out[(long)n * 64 + lane] = fea[j];                 // out[:,0,:]
        float4 p4 = make_float4(P0[j], P1[j], P2[j], P3[j]);
        reinterpret_cast<float4*>(g_P)[n * 32 + lane] = p4;
        g_u[n * 32 + lane] = u[j];
        g_v[n * 32 + lane] = v[j];
        g_agg[n * 32 + lane] = c[j];
    }
}

// ---------------------------------------------------------------------------
// K2: edge stage. 4 edges per warp; 8 lanes per edge; each lane covers 4
// output columns (float4).
//   msg = sum_b w_comp[type][b] * P[src][:,b]
//   z   = relu(u[src] + v[dst] + t[type])
//   a   = sigmoid(dot(z, B_w) + B_b)
//   red.v4(agg[dst], a * msg)
// ---------------------------------------------------------------------------
__global__ void __launch_bounds__(256) k_edge(
    const int* __restrict__ esrc, const int* __restrict__ edst,
    const int* __restrict__ etype, const float* __restrict__ w_comp,
    const float* __restrict__ B_w, const float* __restrict__ B_b, int n_edges) {
    __shared__ __align__(16) float4 s_wc[MAX_RELS];      // w_comp per rel
    __shared__ __align__(16) float4 s_t4[MAX_RELS * 8];  // attn bias per rel
    __shared__ __align__(16) float4 s_bw4[8];
    __shared__ float s_bb;

    int tid = threadIdx.x;
    if (tid < MAX_RELS)
        s_wc[tid] = reinterpret_cast<const float4*>(w_comp)[tid];
    if (tid < MAX_RELS * 8)
        s_t4[tid] = reinterpret_cast<const float4*>(g_t)[tid];
    if (tid < 8)
        s_bw4[tid] = reinterpret_cast<const float4*>(B_w)[tid];
    if (tid == 0) s_bb = B_b[0];
    __syncthreads();

    int warp = (blockIdx.x * blockDim.x + tid) >> 5;
    int lane = tid & 31;
    int sub = lane >> 3;   // edge index within warp (0..3)
    int g = lane & 7;      // lane within 8-lane edge group; outputs 4g..4g+3
    int e = warp * 4 + sub;
    if (e >= n_edges) return;

    int src = esrc[e];
    int dst = edst[e];
    int ty = etype[e];

    const float4* Pp = reinterpret_cast<const float4*>(g_P) + (size_t)src * 32 + g * 4;
    float4 p0 = Pp[0];
    float4 p1 = Pp[1];
    float4 p2 = Pp[2];
    float4 p3 = Pp[3];
    float4 u4 = reinterpret_cast<const float4*>(g_u)[(size_t)src * 8 + g];
    float4 v4 = reinterpret_cast<const float4*>(g_v)[(size_t)dst * 8 + g];
    float4 cc = s_wc[ty];
    float4 t4 = s_t4[ty * 8 + g];
    float4 bw = s_bw4[g];

    float4 msg;
    msg.x = p0.x * cc.x + p0.y * cc.y + p0.z * cc.z + p0.w * cc.w;
    msg.y = p1.x * cc.x + p1.y * cc.y + p1.z * cc.z + p1.w * cc.w;
    msg.z = p2.x * cc.x + p2.y * cc.y + p2.z * cc.z + p2.w * cc.w;
    msg.w = p3.x * cc.x + p3.y * cc.y + p3.z * cc.z + p3.w * cc.w;

    float zx = fmaxf(u4.x + v4.x + t4.x, 0.f);
    float zy = fmaxf(u4.y + v4.y + t4.y, 0.f);
    float zz = fmaxf(u4.z + v4.z + t4.z, 0.f);
    float zw = fmaxf(u4.w + v4.w + t4.w, 0.f);

    float s = zx * bw.x + zy * bw.y + zz * bw.z + zw * bw.w;
    // reduce within 8-lane group (xor offsets 4,2,1 stay inside group)
    s += __shfl_xor_sync(0xffffffffu, s, 4);
    s += __shfl_xor_sync(0xffffffffu, s, 2);
    s += __shfl_xor_sync(0xffffffffu, s, 1);
    float a = 1.f / (1.f + __expf(-(s + s_bb)));

    float4 r = make_float4(a * msg.x, a * msg.y, a * msg.z, a * msg.w);
    atomicAdd(reinterpret_cast<float4*>(g_agg) + (size_t)dst * 8 + g, r);
}

// ---------------------------------------------------------------------------
// K3: h = relu(agg) -> out[:,1,:]  (float4 vectorized)
// ---------------------------------------------------------------------------
__global__ void k_final(float* __restrict__ out, int n4) {
    int i = blockIdx.x * blockDim.x + threadIdx.x;   // over n_nodes*8 float4s
    if (i >= n4) return;
    int n = i >> 3;
    int q = i & 7;
    float4 v = reinterpret_cast<const float4*>(g_agg)[i];
    float4 r = make_float4(fmaxf(v.x, 0.f), fmaxf(v.y, 0.f),
                           fmaxf(v.z, 0.f), fmaxf(v.w, 0.f));
    reinterpret_cast<float4*>(out)[(size_t)n * 16 + 8 + q] = r;
}

extern "C" void kernel_launch(void* const* d_in, const int* in_sizes, int n_in,
                              void* d_out, int out_size) {
    const float* feat      = (const float*)d_in[0];
    const float* embed     = (const float*)d_in[1];
    const float* transform = (const float*)d_in[2];
    const float* weight    = (const float*)d_in[3];
    const float* w_comp    = (const float*)d_in[4];
    const float* selfw     = (const float*)d_in[5];
    const float* A_w       = (const float*)d_in[6];
    const float* A_b       = (const float*)d_in[7];
    const float* B_w       = (const float*)d_in[8];
    const float* B_b       = (const float*)d_in[9];
    const float* attn_emb  = (const float*)d_in[10];
    const int*   idx       = (const int*)d_in[11];
    const int*   esrc      = (const int*)d_in[12];
    const int*   edst      = (const int*)d_in[13];
    const int*   ety       = (const int*)d_in[14];
    float* out = (float*)d_out;

    int n_nodes = in_sizes[0] / 32;
    int n_edges = in_sizes[12];

    k_rel_t<<<1, MAX_RELS * 32>>>(attn_emb, A_w, A_b);

    int warps1 = (n_nodes + 3) / 4;
    int blocks1 = (warps1 * 32 + 255) / 256;
    k_node<<<blocks1, 256>>>(feat, embed, idx, transform, weight, A_w, selfw,
                             out, n_nodes);

    int blocks2 = (n_edges + 31) / 32;  // 8 warps/block, 4 edges/warp
    k_edge<<<blocks2, 256>>>(esrc, edst, ety, w_comp, B_w, B_b, n_edges);

    int n4 = n_nodes * 8;
    int blocks3 = (n4 + 255) / 256;
    k_final<<<blocks3, 256>>>(out, n4);
}

// round 3
// speedup vs baseline: 2.3513x; 1.6126x over previous
#include <cuda_runtime.h>
#include <cuda_fp16.h>
#include <math.h>

#define MAX_NODES 50000
#define MAX_RELS  16
#define D 32

// Scratch (device globals; no allocation allowed)
__device__ __align__(16) __half g_Ph[MAX_NODES * D * 4]; // [n][o][b] halves
__device__ __align__(16) __half g_uh[MAX_NODES * D];     // init_fea @ A_w[0:32]
__device__ __align__(16) __half g_vh[MAX_NODES * D];     // init_fea @ A_w[32:64]
__device__ __align__(16) float  g_agg[MAX_NODES * D];    // curr + scatter of a*msg
__device__ __align__(16) float  g_t[MAX_RELS * D];       // attn_emb @ A_w[64:96] + A_b

struct alignas(8) H4 { __half2 a, b; };

// ---------------------------------------------------------------------------
// K0: per-relation attention bias table t[r][o]
// ---------------------------------------------------------------------------
__global__ void k_rel_t(const float* __restrict__ attn_emb,
                        const float* __restrict__ A_w,
                        const float* __restrict__ A_b) {
    int r = threadIdx.x >> 5;
    int o = threadIdx.x & 31;
    float acc = A_b[o];
#pragma unroll
    for (int k = 0; k < 32; k++)
        acc += attn_emb[r * 32 + k] * A_w[(64 + k) * 32 + o];
    g_t[r * 32 + o] = acc;
}

// ---------------------------------------------------------------------------
// K1: node stage. 4 nodes per warp.
// ---------------------------------------------------------------------------
__global__ void __launch_bounds__(256) k_node(
    const float* __restrict__ feat, const float* __restrict__ embed,
    const int* __restrict__ idx, const float* __restrict__ transform,
    const float* __restrict__ weight, const float* __restrict__ A_w,
    const float* __restrict__ selfw, float* __restrict__ out, int n_nodes) {
    __shared__ float sT[64 * 32];      // transform
    __shared__ float sW[4 * 32 * 32];  // basis weights
    __shared__ float sA[64 * 32];      // A_w rows 0..63
    __shared__ float sS[32 * 32];      // self loop

    int tid = threadIdx.x;
    for (int i = tid; i < 64 * 32; i += blockDim.x) sT[i] = transform[i];
    for (int i = tid; i < 4 * 32 * 32; i += blockDim.x) sW[i] = weight[i];
    for (int i = tid; i < 64 * 32; i += blockDim.x) sA[i] = A_w[i];
    for (int i = tid; i < 32 * 32; i += blockDim.x) sS[i] = selfw[i];
    __syncthreads();

    int warp = (blockIdx.x * blockDim.x + tid) >> 5;
    int lane = tid & 31;
    int n0 = warp * 4;
    if (n0 >= n_nodes) return;

    float f[4], g[4];
    bool val[4];
#pragma unroll
    for (int j = 0; j < 4; j++) {
        int n = n0 + j;
        val[j] = (n < n_nodes);
        if (val[j]) {
            f[j] = feat[n * 32 + lane];
            g[j] = embed[(long)idx[n] * 32 + lane];
        } else {
            f[j] = 0.f; g[j] = 0.f;
        }
    }

    // Phase A: init_fea (lane = output column)
    float fea[4] = {0.f, 0.f, 0.f, 0.f};
#pragma unroll
    for (int k = 0; k < 32; k++) {
        float t1 = sT[k * 32 + lane];
        float t2 = sT[(32 + k) * 32 + lane];
#pragma unroll
        for (int j = 0; j < 4; j++) {
            float fs = __shfl_sync(0xffffffffu, f[j], k);
            float gs = __shfl_sync(0xffffffffu, g[j], k);
            fea[j] += fs * t1 + gs * t2;
        }
    }

    // Phase B: 7 downstream projections of init_fea
    float P0[4] = {0,0,0,0}, P1[4] = {0,0,0,0}, P2[4] = {0,0,0,0}, P3[4] = {0,0,0,0};
    float u[4] = {0,0,0,0}, v[4] = {0,0,0,0}, c[4] = {0,0,0,0};
#pragma unroll
    for (int k = 0; k < 32; k++) {
        float w0 = sW[0 * 1024 + k * 32 + lane];
        float w1 = sW[1 * 1024 + k * 32 + lane];
        float w2 = sW[2 * 1024 + k * 32 + lane];
        float w3 = sW[3 * 1024 + k * 32 + lane];
        float wu = sA[k * 32 + lane];
        float wv = sA[(32 + k) * 32 + lane];
        float wc = sS[k * 32 + lane];
#pragma unroll
        for (int j = 0; j < 4; j++) {
            float s = __shfl_sync(0xffffffffu, fea[j], k);
            P0[j] += s * w0;
            P1[j] += s * w1;
            P2[j] += s * w2;
            P3[j] += s * w3;
            u[j] += s * wu;
            v[j] += s * wv;
            c[j] += s * wc;
        }
    }

#pragma unroll
    for (int j = 0; j < 4; j++) {
        if (!val[j]) continue;
        int n = n0 + j;
        out[(long)n * 64 + lane] = fea[j];                 // out[:,0,:]
        H4 h4;
        h4.a = __halves2half2(__float2half_rn(P0[j]), __float2half_rn(P1[j]));
        h4.b = __halves2half2(__float2half_rn(P2[j]), __float2half_rn(P3[j]));
        *reinterpret_cast<H4*>(&g_Ph[(size_t)n * 128 + lane * 4]) = h4;
        g_uh[n * 32 + lane] = __float2half_rn(u[j]);
        g_vh[n * 32 + lane] = __float2half_rn(v[j]);
        g_agg[n * 32 + lane] = c[j];
    }
}

// ---------------------------------------------------------------------------
// K2: edge stage. 4 edges per warp; 8 lanes per edge; each lane covers 4
// output columns.
// ---------------------------------------------------------------------------
__global__ void __launch_bounds__(256) k_edge(
    const int* __restrict__ esrc, const int* __restrict__ edst,
    const int* __restrict__ etype, const float* __restrict__ w_comp,
    const float* __restrict__ B_w, const float* __restrict__ B_b, int n_edges) {
    __shared__ __align__(16) float4 s_wc[MAX_RELS];      // w_comp per rel
    __shared__ __align__(16) float4 s_t4[MAX_RELS * 8];  // attn bias per rel
    __shared__ __align__(16) float4 s_bw4[8];
    __shared__ float s_bb;

    int tid = threadIdx.x;
    if (tid < MAX_RELS)
        s_wc[tid] = reinterpret_cast<const float4*>(w_comp)[tid];
    if (tid < MAX_RELS * 8)
        s_t4[tid] = reinterpret_cast<const float4*>(g_t)[tid];
    if (tid < 8)
        s_bw4[tid] = reinterpret_cast<const float4*>(B_w)[tid];
    if (tid == 0) s_bb = B_b[0];
    __syncthreads();

    int warp = (blockIdx.x * blockDim.x + tid) >> 5;
    int lane = tid & 31;
    int sub = lane >> 3;   // edge index within warp (0..3)
    int g = lane & 7;      // lane within 8-lane edge group; outputs 4g..4g+3
    int e = warp * 4 + sub;
    if (e >= n_edges) return;

    int src = esrc[e];
    int dst = edst[e];
    int ty = etype[e];

    // P: 16 halves (4 outputs x 4 bases) = 2x LDG.128
    const uint4* Pp = reinterpret_cast<const uint4*>(g_Ph + (size_t)src * 128 + g * 16);
    uint4 r0 = Pp[0];
    uint4 r1 = Pp[1];
    // u, v: 4 halves each = 8 B loads
    uint2 uu = *reinterpret_cast<const uint2*>(g_uh + (size_t)src * 32 + g * 4);
    uint2 vv = *reinterpret_cast<const uint2*>(g_vh + (size_t)dst * 32 + g * 4);

    float4 cc = s_wc[ty];
    float4 t4 = s_t4[ty * 8 + g];
    float4 bw = s_bw4[g];

    float2 p00 = __half22float2(*reinterpret_cast<__half2*>(&r0.x));
    float2 p01 = __half22float2(*reinterpret_cast<__half2*>(&r0.y));
    float2 p10 = __half22float2(*reinterpret_cast<__half2*>(&r0.z));
    float2 p11 = __half22float2(*reinterpret_cast<__half2*>(&r0.w));
    float2 p20 = __half22float2(*reinterpret_cast<__half2*>(&r1.x));
    float2 p21 = __half22float2(*reinterpret_cast<__half2*>(&r1.y));
    float2 p30 = __half22float2(*reinterpret_cast<__half2*>(&r1.z));
    float2 p31 = __half22float2(*reinterpret_cast<__half2*>(&r1.w));

    float4 msg;
    msg.x = p00.x * cc.x + p00.y * cc.y + p01.x * cc.z + p01.y * cc.w;
    msg.y = p10.x * cc.x + p10.y * cc.y + p11.x * cc.z + p11.y * cc.w;
    msg.z = p20.x * cc.x + p20.y * cc.y + p21.x * cc.z + p21.y * cc.w;
    msg.w = p30.x * cc.x + p30.y * cc.y + p31.x * cc.z + p31.y * cc.w;

    float2 u0 = __half22float2(*reinterpret_cast<__half2*>(&uu.x));
    float2 u1 = __half22float2(*reinterpret_cast<__half2*>(&uu.y));
    float2 v0 = __half22float2(*reinterpret_cast<__half2*>(&vv.x));
    float2 v1 = __half22float2(*reinterpret_cast<__half2*>(&vv.y));

    float zx = fmaxf(u0.x + v0.x + t4.x, 0.f);
    float zy = fmaxf(u0.y + v0.y + t4.y, 0.f);
    float zz = fmaxf(u1.x + v1.x + t4.z, 0.f);
    float zw = fmaxf(u1.y + v1.y + t4.w, 0.f);

    float s = zx * bw.x + zy * bw.y + zz * bw.z + zw * bw.w;
    // reduce within 8-lane group (xor offsets 4,2,1 stay inside group)
    s += __shfl_xor_sync(0xffffffffu, s, 4);
    s += __shfl_xor_sync(0xffffffffu, s, 2);
    s += __shfl_xor_sync(0xffffffffu, s, 1);
    float a = 1.f / (1.f + __expf(-(s + s_bb)));

    float4 r = make_float4(a * msg.x, a * msg.y, a * msg.z, a * msg.w);
    atomicAdd(reinterpret_cast<float4*>(g_agg) + (size_t)dst * 8 + g, r);
}

// ---------------------------------------------------------------------------
// K3: h = relu(agg) -> out[:,1,:]  (float4 vectorized)
// ---------------------------------------------------------------------------
__global__ void k_final(float* __restrict__ out, int n4) {
    int i = blockIdx.x * blockDim.x + threadIdx.x;   // over n_nodes*8 float4s
    if (i >= n4) return;
    int n = i >> 3;
    int q = i & 7;
    float4 v = reinterpret_cast<const float4*>(g_agg)[i];
    float4 r = make_float4(fmaxf(v.x, 0.f), fmaxf(v.y, 0.f),
                           fmaxf(v.z, 0.f), fmaxf(v.w, 0.f));
    reinterpret_cast<float4*>(out)[(size_t)n * 16 + 8 + q] = r;
}

extern "C" void kernel_launch(void* const* d_in, const int* in_sizes, int n_in,
                              void* d_out, int out_size) {
    const float* feat      = (const float*)d_in[0];
    const float* embed     = (const float*)d_in[1];
    const float* transform = (const float*)d_in[2];
    const float* weight    = (const float*)d_in[3];
    const float* w_comp    = (const float*)d_in[4];
    const float* selfw     = (const float*)d_in[5];
    const float* A_w       = (const float*)d_in[6];
    const float* A_b       = (const float*)d_in[7];
    const float* B_w       = (const float*)d_in[8];
    const float* B_b       = (const float*)d_in[9];
    const float* attn_emb  = (const float*)d_in[10];
    const int*   idx       = (const int*)d_in[11];
    const int*   esrc      = (const int*)d_in[12];
    const int*   edst      = (const int*)d_in[13];
    const int*   ety       = (const int*)d_in[14];
    float* out = (float*)d_out;

    int n_nodes = in_sizes[0] / 32;
    int n_edges = in_sizes[12];

    k_rel_t<<<1, MAX_RELS * 32>>>(attn_emb, A_w, A_b);

    int warps1 = (n_nodes + 3) / 4;
    int blocks1 = (warps1 * 32 + 255) / 256;
    k_node<<<blocks1, 256>>>(feat, embed, idx, transform, weight, A_w, selfw,
                             out, n_nodes);

    int blocks2 = (n_edges + 31) / 32;  // 8 warps/block, 4 edges/warp
    k_edge<<<blocks2, 256>>>(esrc, edst, ety, w_comp, B_w, B_b, n_edges);

    int n4 = n_nodes * 8;
    int blocks3 = (n4 + 255) / 256;
    k_final<<<blocks3, 256>>>(out, n4);
}